// round 6
// baseline (speedup 1.0000x reference)
#include <cuda_runtime.h>
#include <cstdint>

// Problem constants
#define BATCH   8192
#define IN_DIM  256
#define HID_DIM 16384
#define OUT_DIM 256
#define TOPK    256

// ---------------------------------------------------------------------------
// Device scratch (no allocations allowed): transposed decoder weights.
// g_dwt[n][o] = dec_w[o][n]  -> 16 MB, L2-resident during the decode pass.
// ---------------------------------------------------------------------------
__device__ float g_dwt[(size_t)HID_DIM * OUT_DIM];

// ---------------------------------------------------------------------------
// f32x2 packed helpers (sm_100+ PTX; SASS FFMA2 — 2x fp32 FMA throughput)
// ---------------------------------------------------------------------------
__device__ __forceinline__ unsigned long long pack_dup(float v) {
    unsigned long long r;
    unsigned int u = __float_as_uint(v);
    asm("mov.b64 %0, {%1, %1};" : "=l"(r) : "r"(u));
    return r;
}
__device__ __forceinline__ void ffma2(unsigned long long& d,
                                      unsigned long long a,
                                      unsigned long long b) {
    asm("fma.rn.f32x2 %0, %1, %2, %0;" : "+l"(d) : "l"(a), "l"(b));
}
__device__ __forceinline__ float lo32(unsigned long long v) {
    return __uint_as_float((unsigned int)(v & 0xffffffffull));
}
__device__ __forceinline__ float hi32(unsigned long long v) {
    return __uint_as_float((unsigned int)(v >> 32));
}

// ---------------------------------------------------------------------------
// Kernel 0: transpose dec_w (OUT x HID) -> g_dwt (HID x OUT)
// ---------------------------------------------------------------------------
__global__ void transpose_kernel(const float* __restrict__ dw) {
    __shared__ float tile[32][33];
    const int n0 = blockIdx.x * 32;
    const int o0 = blockIdx.y * 32;
    const int tx = threadIdx.x;
    const int ty = threadIdx.y;
#pragma unroll
    for (int j = 0; j < 4; j++) {
        tile[ty + j * 8][tx] =
            dw[(size_t)(o0 + ty + j * 8) * HID_DIM + n0 + tx];
    }
    __syncthreads();
#pragma unroll
    for (int j = 0; j < 4; j++) {
        g_dwt[(size_t)(n0 + ty + j * 8) * OUT_DIM + o0 + tx] =
            tile[tx][ty + j * 8];
    }
}

// ---------------------------------------------------------------------------
// Kernel 1: fp32 GEMM  h[m][n] = relu( sum_k x[m][k]*enc_w[n][k] + enc_b[n] )
// M=8192, N=16384, K=256.  128x128 CTA tile, BK=16, 256 threads, 8x8 per
// thread as 8 rows x 4 f32x2 column-pairs.  Register double-buffered loads.
// ---------------------------------------------------------------------------
__global__ __launch_bounds__(256, 2)
void gemm1_kernel(const float* __restrict__ A,     // x        [M][256]
                  const float* __restrict__ B,     // enc_w    [N][256]
                  const float* __restrict__ bias,  // enc_b    [N]
                  float* __restrict__ C) {         // h (relu) [M][N]
    __shared__ float As[16][132];
    __shared__ float Bs[16][132];

    const int tid = threadIdx.x;
    const int bm = blockIdx.y * 128;
    const int bn = blockIdx.x * 128;
    const int tx = tid & 15;   // column group (8 cols)
    const int ty = tid >> 4;   // row group    (8 rows)
    const int lr = tid >> 2;   // load row within tile (0..63)
    const int lk = (tid & 3) * 4;  // load k offset (0,4,8,12)

    const float* Aptr = A + (size_t)(bm + lr) * IN_DIM + lk;
    const float* Bptr = B + (size_t)(bn + lr) * IN_DIM + lk;

    unsigned long long acc[8][4];
#pragma unroll
    for (int j = 0; j < 8; j++)
#pragma unroll
        for (int c = 0; c < 4; c++) acc[j][c] = 0ull;

    float4 pa0, pa1, pb0, pb1;

    // ---- load chunk 0
    pa0 = *(const float4*)(Aptr);
    pa1 = *(const float4*)(Aptr + 64 * IN_DIM);
    pb0 = *(const float4*)(Bptr);
    pb1 = *(const float4*)(Bptr + 64 * IN_DIM);
    {
        As[lk + 0][lr] = pa0.x; As[lk + 1][lr] = pa0.y;
        As[lk + 2][lr] = pa0.z; As[lk + 3][lr] = pa0.w;
        As[lk + 0][lr + 64] = pa1.x; As[lk + 1][lr + 64] = pa1.y;
        As[lk + 2][lr + 64] = pa1.z; As[lk + 3][lr + 64] = pa1.w;
        Bs[lk + 0][lr] = pb0.x; Bs[lk + 1][lr] = pb0.y;
        Bs[lk + 2][lr] = pb0.z; Bs[lk + 3][lr] = pb0.w;
        Bs[lk + 0][lr + 64] = pb1.x; Bs[lk + 1][lr + 64] = pb1.y;
        Bs[lk + 2][lr + 64] = pb1.z; Bs[lk + 3][lr + 64] = pb1.w;
    }
    __syncthreads();

    auto compute = [&]() {
#pragma unroll
        for (int k = 0; k < 16; k++) {
            float4 a0 = *(const float4*)&As[k][ty * 8];
            float4 a1 = *(const float4*)&As[k][ty * 8 + 4];
            ulonglong2 b0 = *(const ulonglong2*)&Bs[k][tx * 8];
            ulonglong2 b1 = *(const ulonglong2*)&Bs[k][tx * 8 + 4];
            unsigned long long bv[4] = { b0.x, b0.y, b1.x, b1.y };
            float av[8] = { a0.x, a0.y, a0.z, a0.w, a1.x, a1.y, a1.z, a1.w };
#pragma unroll
            for (int j = 0; j < 8; j++) {
                unsigned long long ad = pack_dup(av[j]);
#pragma unroll
                for (int c = 0; c < 4; c++) ffma2(acc[j][c], ad, bv[c]);
            }
        }
    };

#pragma unroll 1
    for (int kc = 0; kc < 15; kc++) {
        const float* Ap = Aptr + (kc + 1) * 16;
        const float* Bp = Bptr + (kc + 1) * 16;
        pa0 = *(const float4*)(Ap);
        pa1 = *(const float4*)(Ap + 64 * IN_DIM);
        pb0 = *(const float4*)(Bp);
        pb1 = *(const float4*)(Bp + 64 * IN_DIM);

        compute();

        __syncthreads();
        As[lk + 0][lr] = pa0.x; As[lk + 1][lr] = pa0.y;
        As[lk + 2][lr] = pa0.z; As[lk + 3][lr] = pa0.w;
        As[lk + 0][lr + 64] = pa1.x; As[lk + 1][lr + 64] = pa1.y;
        As[lk + 2][lr + 64] = pa1.z; As[lk + 3][lr + 64] = pa1.w;
        Bs[lk + 0][lr] = pb0.x; Bs[lk + 1][lr] = pb0.y;
        Bs[lk + 2][lr] = pb0.z; Bs[lk + 3][lr] = pb0.w;
        Bs[lk + 0][lr + 64] = pb1.x; Bs[lk + 1][lr + 64] = pb1.y;
        Bs[lk + 2][lr + 64] = pb1.z; Bs[lk + 3][lr + 64] = pb1.w;
        __syncthreads();
    }
    compute();  // last chunk

    // ---- epilogue: + bias, relu, store
    float bias8[8];
    *(float4*)&bias8[0] = *(const float4*)&bias[bn + tx * 8];
    *(float4*)&bias8[4] = *(const float4*)&bias[bn + tx * 8 + 4];

#pragma unroll
    for (int j = 0; j < 8; j++) {
        float o[8];
#pragma unroll
        for (int c = 0; c < 4; c++) {
            o[2 * c + 0] = lo32(acc[j][c]);
            o[2 * c + 1] = hi32(acc[j][c]);
        }
#pragma unroll
        for (int i = 0; i < 8; i++) o[i] = fmaxf(o[i] + bias8[i], 0.0f);
        size_t off = (size_t)(bm + ty * 8 + j) * HID_DIM + bn + tx * 8;
        *(float4*)&C[off]     = make_float4(o[0], o[1], o[2], o[3]);
        *(float4*)&C[off + 4] = make_float4(o[4], o[5], o[6], o[7]);
    }
}

// ---------------------------------------------------------------------------
// Kernel 2 (fused): per-row exact radix top-k threshold + masked writeback +
// sparse decoder GEMM.  One CTA (256 threads) per batch row.
//   - row (16384 fp32) -> smem as uint keys (relu output >= +0.0, so float
//     bit pattern is monotone -> radix-select gives the bit-exact k-th
//     largest including duplicates, matching jax's  h >= topk_vals[:,-1]).
//   - masked h written back in place (becomes hidden_post output).
//   - out[row][o] = sum over survivors v * dwt[n][o] + dec_b[o]
//     (dwt gathered from L2; ~256 x 1KB coalesced rows per CTA).
// ---------------------------------------------------------------------------
struct FusedSmem {
    unsigned int keys[HID_DIM];   // 65536 B
    float        vals[4096];      // 16384 B
    int          idxs[4096];      // 16384 B
    unsigned int hist[256];       //  1024 B
    int          cnt;
    unsigned int sh_prefix;
    int          sh_krem;
};

__global__ void fused_topk_decode_kernel(float* __restrict__ hid,
                                         const float* __restrict__ dec_b,
                                         float* __restrict__ out) {
    extern __shared__ unsigned char smem_raw[];
    FusedSmem& s = *reinterpret_cast<FusedSmem*>(smem_raw);

    const int t = threadIdx.x;            // 0..255
    const int row = blockIdx.x;
    float* hrow = hid + (size_t)row * HID_DIM;

    // ---- load row into smem (as bit keys), float4 coalesced
#pragma unroll
    for (int i = 0; i < 16; i++) {
        int n4 = i * 256 + t;             // float4 index
        float4 v = *(const float4*)(hrow + (size_t)n4 * 4);
        uint4 u;
        u.x = __float_as_uint(v.x); u.y = __float_as_uint(v.y);
        u.z = __float_as_uint(v.z); u.w = __float_as_uint(v.w);
        *(uint4*)&s.keys[n4 * 4] = u;
    }

    // ---- 4-round MSB radix select for the TOPK-th largest key
    unsigned int prefix = 0, maskhi = 0;
    int krem = TOPK;
#pragma unroll 1
    for (int r = 0; r < 4; r++) {
        const int shift = 24 - r * 8;
        s.hist[t] = 0;
        __syncthreads();
#pragma unroll 4
        for (int i = 0; i < 64; i++) {
            unsigned int key = s.keys[i * 256 + t];
            if ((key & maskhi) == prefix)
                atomicAdd(&s.hist[(key >> shift) & 255u], 1u);
        }
        __syncthreads();
        if (t == 0) {
            unsigned int cum = 0;
            int d = 255;
            for (; d > 0; d--) {
                unsigned int c = s.hist[d];
                if (cum + c >= (unsigned int)krem) break;
                cum += c;
            }
            s.sh_prefix = prefix | ((unsigned int)d << shift);
            s.sh_krem = krem - (int)cum;
        }
        __syncthreads();
        prefix = s.sh_prefix;
        krem = s.sh_krem;
        maskhi |= (0xFFu << shift);
    }
    const float thr = __uint_as_float(prefix);

    // ---- masked writeback + compaction + sparse decode (4 chunks of 4096)
    float acc = 0.0f;
#pragma unroll 1
    for (int c = 0; c < 4; c++) {
        if (t == 0) s.cnt = 0;
        __syncthreads();
        const int base = c * 4096;
#pragma unroll
        for (int i = 0; i < 16; i++) {
            int n = base + i * 256 + t;
            float v = __uint_as_float(s.keys[n]);
            bool keep = (v >= thr);
            hrow[n] = keep ? v : 0.0f;
            if (keep) {
                int p = atomicAdd(&s.cnt, 1);
                s.vals[p] = v;
                s.idxs[p] = n;
            }
        }
        __syncthreads();
        const int m = s.cnt;
#pragma unroll 4
        for (int j = 0; j < m; j++) {
            acc = fmaf(s.vals[j], g_dwt[(size_t)s.idxs[j] * OUT_DIM + t], acc);
        }
        __syncthreads();
    }
    out[(size_t)row * OUT_DIM + t] = acc + dec_b[t];
}

// ---------------------------------------------------------------------------
// kernel_launch
//   inputs: 0=x, 1=enc_w, 2=enc_b, 3=dec_w, 4=dec_b, 5=k (fixed 256)
//   output: [output (8192*256) | hidden_post (8192*16384)] fp32
// ---------------------------------------------------------------------------
extern "C" void kernel_launch(void* const* d_in, const int* in_sizes, int n_in,
                              void* d_out, int out_size) {
    const float* x     = (const float*)d_in[0];
    const float* enc_w = (const float*)d_in[1];
    const float* enc_b = (const float*)d_in[2];
    const float* dec_w = (const float*)d_in[3];
    const float* dec_b = (const float*)d_in[4];

    float* out = (float*)d_out;
    float* hid = out + (size_t)BATCH * OUT_DIM;

    // idempotent; needed for ~97 KB dynamic smem in the fused kernel
    cudaFuncSetAttribute(fused_topk_decode_kernel,
                         cudaFuncAttributeMaxDynamicSharedMemorySize,
                         (int)sizeof(FusedSmem));

    // k0: transpose decoder weights into device-global scratch
    transpose_kernel<<<dim3(HID_DIM / 32, OUT_DIM / 32), dim3(32, 8)>>>(dec_w);

    // k1: encoder GEMM + bias + relu  -> hidden region of d_out
    gemm1_kernel<<<dim3(HID_DIM / 128, BATCH / 128), 256>>>(x, enc_w, enc_b, hid);

    // k2: fused exact top-k threshold, masking, sparse decoder GEMM
    fused_topk_decode_kernel<<<BATCH, 256, sizeof(FusedSmem)>>>(hid, dec_b, out);
}

// round 9
// speedup vs baseline: 1.0468x; 1.0468x over previous
#include <cuda_runtime.h>
#include <cuda_bf16.h>
#include <cstdint>

// Problem constants
#define BATCH   8192
#define IN_DIM  256
#define HID_DIM 16384
#define OUT_DIM 256
#define TOPK    256

// ---------------------------------------------------------------------------
// Device scratch (no allocations allowed)
// ---------------------------------------------------------------------------
__device__ float g_dwt[(size_t)HID_DIM * OUT_DIM];                      // dec_w^T
__device__ __align__(256) __nv_bfloat16 g_xs[3][(size_t)BATCH * IN_DIM];   // x splits
__device__ __align__(256) __nv_bfloat16 g_ws[3][(size_t)HID_DIM * IN_DIM]; // w splits

// ---------------------------------------------------------------------------
// Portable PTX helpers (valid on plain sm_103 target: sm_80+ baseline)
// ---------------------------------------------------------------------------
__device__ __forceinline__ uint32_t smem_to_u32(const void* p) {
    uint32_t a;
    asm("{ .reg .u64 t; cvta.to.shared.u64 t, %1; cvt.u32.u64 %0, t; }"
        : "=r"(a) : "l"(p));
    return a;
}

#define CP_ASYNC16(dst_u32, src_ptr) \
    asm volatile("cp.async.cg.shared.global [%0], [%1], 16;" \
                 :: "r"(dst_u32), "l"(src_ptr) : "memory")
#define CP_COMMIT()  asm volatile("cp.async.commit_group;" ::: "memory")
#define CP_WAIT(N)   asm volatile("cp.async.wait_group %0;" :: "n"(N) : "memory")

#define LDSM_X4(r, addr) \
    asm volatile("ldmatrix.sync.aligned.m8n8.x4.shared.b16 {%0,%1,%2,%3}, [%4];" \
                 : "=r"((r)[0]), "=r"((r)[1]), "=r"((r)[2]), "=r"((r)[3]) \
                 : "r"(addr))
#define LDSM_X2(r, addr) \
    asm volatile("ldmatrix.sync.aligned.m8n8.x2.shared.b16 {%0,%1}, [%2];" \
                 : "=r"((r)[0]), "=r"((r)[1]) : "r"(addr))

// D(16x8,f32) += A(16x16,bf16,row) * B(16x8,bf16,col)
#define MMA_BF16(d, a, b) \
    asm volatile("mma.sync.aligned.m16n8k16.row.col.f32.bf16.bf16.f32 " \
                 "{%0,%1,%2,%3}, {%4,%5,%6,%7}, {%8,%9}, {%0,%1,%2,%3};" \
                 : "+f"((d)[0]), "+f"((d)[1]), "+f"((d)[2]), "+f"((d)[3]) \
                 : "r"((a)[0]), "r"((a)[1]), "r"((a)[2]), "r"((a)[3]), \
                   "r"((b)[0]), "r"((b)[1]))

// ---------------------------------------------------------------------------
// Split kernels: fp32 -> 3 bf16 components (x = b0 + b1 + b2 + O(2^-27))
// ---------------------------------------------------------------------------
__device__ __forceinline__ void split3(float v, __nv_bfloat16& b0,
                                       __nv_bfloat16& b1, __nv_bfloat16& b2) {
    b0 = __float2bfloat16(v);
    float r1 = v - __bfloat162float(b0);
    b1 = __float2bfloat16(r1);
    float r2 = r1 - __bfloat162float(b1);
    b2 = __float2bfloat16(r2);
}

__global__ void split_x_kernel(const float* __restrict__ src) {
    int i = blockIdx.x * blockDim.x + threadIdx.x;
    if (i >= BATCH * IN_DIM) return;
    __nv_bfloat16 b0, b1, b2;
    split3(src[i], b0, b1, b2);
    g_xs[0][i] = b0; g_xs[1][i] = b1; g_xs[2][i] = b2;
}

__global__ void split_w_kernel(const float* __restrict__ src) {
    int i = blockIdx.x * blockDim.x + threadIdx.x;
    if (i >= HID_DIM * IN_DIM) return;
    __nv_bfloat16 b0, b1, b2;
    split3(src[i], b0, b1, b2);
    g_ws[0][i] = b0; g_ws[1][i] = b1; g_ws[2][i] = b2;
}

// ---------------------------------------------------------------------------
// Kernel 0: transpose dec_w (OUT x HID) -> g_dwt (HID x OUT)
// ---------------------------------------------------------------------------
__global__ void transpose_kernel(const float* __restrict__ dw) {
    __shared__ float tile[32][33];
    const int n0 = blockIdx.x * 32;
    const int o0 = blockIdx.y * 32;
    const int tx = threadIdx.x;
    const int ty = threadIdx.y;
#pragma unroll
    for (int j = 0; j < 4; j++) {
        tile[ty + j * 8][tx] =
            dw[(size_t)(o0 + ty + j * 8) * HID_DIM + n0 + tx];
    }
    __syncthreads();
#pragma unroll
    for (int j = 0; j < 4; j++) {
        g_dwt[(size_t)(n0 + ty + j * 8) * OUT_DIM + o0 + tx] =
            tile[tx][ty + j * 8];
    }
}

// ---------------------------------------------------------------------------
// Kernel 1: HMMA bf16 3-split GEMM (abs err ~1e-5; decisions fixed later)
//   h[m][n] = relu( sum_k x[m][k]*enc_w[n][k] + enc_b[n] )
// 128x128 CTA, 8 warps (32x64 each), K in 4 chunks of 64, cp.async double
// buffer of 6 bf16 planes, 6 cross products.
// ---------------------------------------------------------------------------
#define STRIDE_B     144                        // 64 bf16 = 128B + 16B pad
#define PLANE_BYTES  (128 * STRIDE_B)           // 18432
#define BUF_BYTES    (6 * PLANE_BYTES)          // 110592
#define GEMM_SMEM    (2 * BUF_BYTES)            // 221184

__global__ __launch_bounds__(256, 1)
void gemm_mma_kernel(const float* __restrict__ bias, float* __restrict__ C) {
    extern __shared__ unsigned char smem[];
    const uint32_t sb = smem_to_u32(smem);
    const int t = threadIdx.x;
    const int wid = t >> 5;
    const int lane = t & 31;
    const int bm = blockIdx.y * 128;
    const int bn = blockIdx.x * 128;
    const int m0 = (wid & 3) * 32;              // warp row base within tile
    const int n0 = (wid >> 2) * 64;             // warp col base within tile

    const __nv_bfloat16* planes[6] = {
        g_xs[0] + (size_t)bm * IN_DIM, g_xs[1] + (size_t)bm * IN_DIM,
        g_xs[2] + (size_t)bm * IN_DIM,
        g_ws[0] + (size_t)bn * IN_DIM, g_ws[1] + (size_t)bn * IN_DIM,
        g_ws[2] + (size_t)bn * IN_DIM };

    float acc[2][8][4];
#pragma unroll
    for (int mt = 0; mt < 2; mt++)
#pragma unroll
        for (int nt = 0; nt < 8; nt++)
#pragma unroll
            for (int i = 0; i < 4; i++) acc[mt][nt][i] = 0.0f;

    auto load_chunk = [&](int buf, int c) {
#pragma unroll
        for (int p = 0; p < 6; p++) {
            const unsigned char* srcp = (const unsigned char*)planes[p];
#pragma unroll
            for (int i = 0; i < 4; i++) {
                int g = i * 256 + t;            // 0..1023 16B units
                int row = g >> 3;
                int seg = g & 7;
                const unsigned char* src =
                    srcp + ((size_t)row * IN_DIM + c * 64 + seg * 8) * 2;
                uint32_t dst = sb + buf * BUF_BYTES + p * PLANE_BYTES +
                               row * STRIDE_B + seg * 16;
                CP_ASYNC16(dst, src);
            }
        }
        CP_COMMIT();
    };

    auto compute_chunk = [&](int buf) {
        const uint32_t ab = sb + buf * BUF_BYTES;
#pragma unroll
        for (int j = 0; j < 4; j++) {           // k-steps of 16
            uint32_t af[3][2][4];
#pragma unroll
            for (int ap = 0; ap < 3; ap++)
#pragma unroll
                for (int mt = 0; mt < 2; mt++) {
                    uint32_t addr = ab + ap * PLANE_BYTES +
                        (uint32_t)(m0 + 16 * mt + (lane & 15)) * STRIDE_B +
                        j * 32 + (lane >> 4) * 16;
                    LDSM_X4(af[ap][mt], addr);
                }
#pragma unroll
            for (int bp = 0; bp < 3; bp++) {
                uint32_t bf[8][2];
                const int l = lane & 15;
#pragma unroll
                for (int nt = 0; nt < 8; nt++) {
                    uint32_t addr = ab + (3 + bp) * PLANE_BYTES +
                        (uint32_t)(n0 + 8 * nt + (l & 7)) * STRIDE_B +
                        j * 32 + (l >> 3) * 16;
                    LDSM_X2(bf[nt], addr);
                }
                const int na = (bp == 0) ? 3 : (bp == 1) ? 2 : 1;
#pragma unroll
                for (int ap = 0; ap < 3; ap++) {
                    if (ap >= na) break;
#pragma unroll
                    for (int mt = 0; mt < 2; mt++)
#pragma unroll
                        for (int nt = 0; nt < 8; nt++)
                            MMA_BF16(acc[mt][nt], af[ap][mt], bf[nt]);
                }
            }
        }
    };

    load_chunk(0, 0);
    load_chunk(1, 1);

    CP_WAIT(1); __syncthreads();
    compute_chunk(0);
    __syncthreads();
    load_chunk(0, 2);

    CP_WAIT(1); __syncthreads();
    compute_chunk(1);
    __syncthreads();
    load_chunk(1, 3);

    CP_WAIT(1); __syncthreads();
    compute_chunk(0);

    CP_WAIT(0); __syncthreads();
    compute_chunk(1);

    // ---- epilogue: + bias, relu, store
#pragma unroll
    for (int mt = 0; mt < 2; mt++) {
        const int r0 = bm + m0 + 16 * mt + (lane >> 2);
#pragma unroll
        for (int nt = 0; nt < 8; nt++) {
            const int col = bn + n0 + 8 * nt + 2 * (lane & 3);
            const float bv0 = __ldg(bias + col);
            const float bv1 = __ldg(bias + col + 1);
            float2 v0, v1;
            v0.x = fmaxf(acc[mt][nt][0] + bv0, 0.0f);
            v0.y = fmaxf(acc[mt][nt][1] + bv1, 0.0f);
            v1.x = fmaxf(acc[mt][nt][2] + bv0, 0.0f);
            v1.y = fmaxf(acc[mt][nt][3] + bv1, 0.0f);
            *(float2*)&C[(size_t)r0 * HID_DIM + col] = v0;
            *(float2*)&C[(size_t)(r0 + 8) * HID_DIM + col] = v1;
        }
    }
}

// ---------------------------------------------------------------------------
// Kernel 2 (fused): radix top-k threshold on noisy h + EXACT boundary-band
// recheck (fp32 recompute of ~13 candidates/row) + masked writeback + sparse
// decoder GEMM.  One CTA (256 threads) per batch row.
//
// Correctness: |h_noisy - h_exact| <= eps << DELTA/2.  Then
//   v > thr+DELTA  => exactly above the true k-th largest  -> keep
//   v < thr-DELTA  => exactly below                        -> drop
//   band           => recompute exact fp32 value; keep the top (k - n_hi)
//                     band values with >=-ties (reference's h >= thr rule).
// ---------------------------------------------------------------------------
#define DELTA     1e-2f
#define BAND_CAP  256

struct FusedSmem {
    unsigned int keys[HID_DIM];   // 65536 B
    float        vals[4096];      // 16384 B
    int          idxs[4096];      // 16384 B
    unsigned int hist[256];       //  1024 B
    float        x_row[IN_DIM];   //  1024 B
    float        band_exact[BAND_CAP]; // 1024 B
    int          band_idx[BAND_CAP];   // 1024 B
    int          band_keep[BAND_CAP];  // 1024 B
    int          cnt;
    unsigned int sh_prefix;
    int          sh_krem;
    int          n_hi;
    int          band_cnt;
};

__global__ __launch_bounds__(256)
void fused_topk_decode_kernel(float* __restrict__ hid,
                              const float* __restrict__ x,
                              const float* __restrict__ enc_w,
                              const float* __restrict__ enc_b,
                              const float* __restrict__ dec_b,
                              float* __restrict__ out) {
    extern __shared__ unsigned char smem_raw[];
    FusedSmem& s = *reinterpret_cast<FusedSmem*>(smem_raw);

    const int t = threadIdx.x;            // 0..255
    const int wid = t >> 5;
    const int lane = t & 31;
    const int row = blockIdx.x;
    float* hrow = hid + (size_t)row * HID_DIM;

    // ---- load row into smem (as bit keys) + x row for exact recompute
    s.x_row[t] = x[(size_t)row * IN_DIM + t];
#pragma unroll
    for (int i = 0; i < 16; i++) {
        int n4 = i * 256 + t;             // float4 index
        float4 v = *(const float4*)(hrow + (size_t)n4 * 4);
        uint4 u;
        u.x = __float_as_uint(v.x); u.y = __float_as_uint(v.y);
        u.z = __float_as_uint(v.z); u.w = __float_as_uint(v.w);
        *(uint4*)&s.keys[n4 * 4] = u;
    }

    // ---- 4-round MSB radix select for the TOPK-th largest (noisy) key
    unsigned int prefix = 0, maskhi = 0;
    int krem = TOPK;
#pragma unroll 1
    for (int r = 0; r < 4; r++) {
        const int shift = 24 - r * 8;
        s.hist[t] = 0;
        __syncthreads();
#pragma unroll 4
        for (int i = 0; i < 64; i++) {
            unsigned int key = s.keys[i * 256 + t];
            if ((key & maskhi) == prefix)
                atomicAdd(&s.hist[(key >> shift) & 255u], 1u);
        }
        __syncthreads();
        if (t == 0) {
            unsigned int cum = 0;
            int d = 255;
            for (; d > 0; d--) {
                unsigned int c = s.hist[d];
                if (cum + c >= (unsigned int)krem) break;
                cum += c;
            }
            s.sh_prefix = prefix | ((unsigned int)d << shift);
            s.sh_krem = krem - (int)cum;
        }
        __syncthreads();
        prefix = s.sh_prefix;
        krem = s.sh_krem;
        maskhi |= (0xFFu << shift);
    }
    const float thr = __uint_as_float(prefix);
    const float thr_hi = thr + DELTA;
    const float thr_lo = thr - DELTA;

    // ---- classification pass: count sure-keeps, collect band candidates
    if (t == 0) { s.n_hi = 0; s.band_cnt = 0; }
    __syncthreads();
    {
        int my_hi = 0;
#pragma unroll 4
        for (int i = 0; i < 64; i++) {
            int n = i * 256 + t;
            float v = __uint_as_float(s.keys[n]);
            if (v > thr_hi) {
                my_hi++;
            } else if (v >= thr_lo) {
                int p = atomicAdd(&s.band_cnt, 1);
                if (p < BAND_CAP) s.band_idx[p] = n;
            }
        }
        // warp-reduce hi count, one atomic per warp
#pragma unroll
        for (int off = 16; off; off >>= 1)
            my_hi += __shfl_xor_sync(0xFFFFFFFFu, my_hi, off);
        if (lane == 0 && my_hi) atomicAdd(&s.n_hi, my_hi);
    }
    __syncthreads();
    const int bc = min(s.band_cnt, BAND_CAP);
    const int n_hi = s.n_hi;

    // ---- exact fp32 recompute of band candidates (one warp per candidate)
    for (int b = wid; b < bc; b += 8) {
        const int n = s.band_idx[b];
        const float* wrow = enc_w + (size_t)n * IN_DIM;
        float4 xa = *(const float4*)&s.x_row[lane * 8];
        float4 xb = *(const float4*)&s.x_row[lane * 8 + 4];
        float4 wa = *(const float4*)&wrow[lane * 8];
        float4 wb = *(const float4*)&wrow[lane * 8 + 4];
        float p = xa.x * wa.x;
        p = fmaf(xa.y, wa.y, p);
        p = fmaf(xa.z, wa.z, p);
        p = fmaf(xa.w, wa.w, p);
        p = fmaf(xb.x, wb.x, p);
        p = fmaf(xb.y, wb.y, p);
        p = fmaf(xb.z, wb.z, p);
        p = fmaf(xb.w, wb.w, p);
#pragma unroll
        for (int off = 16; off; off >>= 1)
            p += __shfl_xor_sync(0xFFFFFFFFu, p, off);
        if (lane == 0)
            s.band_exact[b] = fmaxf(p + __ldg(enc_b + n), 0.0f);
    }
    __syncthreads();

    // ---- band selection: keep top (TOPK - n_hi) exact values, >= ties kept
    if (wid == 0) {
        const int kr = TOPK - n_hi;   // >= 1 by construction
        for (int i = lane; i < bc; i += 32) {
            float ei = s.band_exact[i];
            int cnt = 0;
            for (int j = 0; j < bc; j++)
                cnt += (s.band_exact[j] > ei) ? 1 : 0;
            s.band_keep[i] = (cnt < kr) ? 1 : 0;
        }
    }
    __syncthreads();

    // ---- masked writeback + compaction + sparse decode (4 chunks of 4096)
    float acc = 0.0f;
#pragma unroll 1
    for (int c = 0; c < 4; c++) {
        if (t == 0) s.cnt = 0;
        __syncthreads();
        const int base = c * 4096;
#pragma unroll
        for (int i = 0; i < 16; i++) {
            int n = base + i * 256 + t;
            float v = __uint_as_float(s.keys[n]);
            bool keep;
            float outv;
            if (v > thr_hi) {
                keep = true; outv = v;
            } else if (v >= thr_lo) {
                keep = false; outv = 0.0f;       // rare path: scan band list
                for (int b = 0; b < bc; b++) {
                    if (s.band_idx[b] == n) {
                        keep = (s.band_keep[b] != 0);
                        outv = s.band_exact[b];
                        break;
                    }
                }
                if (!keep) outv = 0.0f;
            } else {
                keep = false; outv = 0.0f;
            }
            hrow[n] = keep ? outv : 0.0f;
            if (keep) {
                int p = atomicAdd(&s.cnt, 1);
                s.vals[p] = outv;
                s.idxs[p] = n;
            }
        }
        __syncthreads();
        const int m = s.cnt;
#pragma unroll 4
        for (int j = 0; j < m; j++) {
            acc = fmaf(s.vals[j], g_dwt[(size_t)s.idxs[j] * OUT_DIM + t], acc);
        }
        __syncthreads();
    }
    out[(size_t)row * OUT_DIM + t] = acc + dec_b[t];
}

// ---------------------------------------------------------------------------
// kernel_launch
//   inputs: 0=x, 1=enc_w, 2=enc_b, 3=dec_w, 4=dec_b, 5=k (fixed 256)
//   output: [output (8192*256) | hidden_post (8192*16384)] fp32
// ---------------------------------------------------------------------------
extern "C" void kernel_launch(void* const* d_in, const int* in_sizes, int n_in,
                              void* d_out, int out_size) {
    const float* x     = (const float*)d_in[0];
    const float* enc_w = (const float*)d_in[1];
    const float* enc_b = (const float*)d_in[2];
    const float* dec_w = (const float*)d_in[3];
    const float* dec_b = (const float*)d_in[4];

    float* out = (float*)d_out;
    float* hid = out + (size_t)BATCH * OUT_DIM;

    // idempotent attribute setup (host-side, not captured)
    cudaFuncSetAttribute(fused_topk_decode_kernel,
                         cudaFuncAttributeMaxDynamicSharedMemorySize,
                         (int)sizeof(FusedSmem));
    cudaFuncSetAttribute(gemm_mma_kernel,
                         cudaFuncAttributeMaxDynamicSharedMemorySize,
                         GEMM_SMEM);

    // prep: 3-way bf16 splits of x and enc_w; dec_w transpose
    split_x_kernel<<<(BATCH * IN_DIM + 255) / 256, 256>>>(x);
    split_w_kernel<<<(HID_DIM * IN_DIM + 255) / 256, 256>>>(enc_w);
    transpose_kernel<<<dim3(HID_DIM / 32, OUT_DIM / 32), dim3(32, 8)>>>(dec_w);

    // k1: HMMA bf16 3-split encoder GEMM + bias + relu
    gemm_mma_kernel<<<dim3(HID_DIM / 128, BATCH / 128), 256, GEMM_SMEM>>>(enc_b, hid);

    // k2: fused top-k with exact boundary-band recheck + sparse decoder GEMM
    fused_topk_decode_kernel<<<BATCH, 256, sizeof(FusedSmem)>>>(
        hid, x, enc_w, enc_b, dec_b, out);
}

// round 10
// speedup vs baseline: 2.2358x; 2.1359x over previous
#include <cuda_runtime.h>
#include <cuda_bf16.h>
#include <cstdint>

// Problem constants
#define BATCH   8192
#define IN_DIM  256
#define HID_DIM 16384
#define OUT_DIM 256
#define TOPK    256

// ---------------------------------------------------------------------------
// Device scratch (no allocations allowed)
// ---------------------------------------------------------------------------
__device__ float g_dwt[(size_t)HID_DIM * OUT_DIM];                      // dec_w^T
__device__ __align__(256) __nv_bfloat16 g_xs[2][(size_t)BATCH * IN_DIM];   // x splits
__device__ __align__(256) __nv_bfloat16 g_ws[2][(size_t)HID_DIM * IN_DIM]; // w splits

// ---------------------------------------------------------------------------
// Portable PTX helpers (plain sm_103 target: sm_80+ baseline only)
// ---------------------------------------------------------------------------
__device__ __forceinline__ uint32_t smem_to_u32(const void* p) {
    uint32_t a;
    asm("{ .reg .u64 t; cvta.to.shared.u64 t, %1; cvt.u32.u64 %0, t; }"
        : "=r"(a) : "l"(p));
    return a;
}

#define CP_ASYNC16(dst_u32, src_ptr) \
    asm volatile("cp.async.cg.shared.global [%0], [%1], 16;" \
                 :: "r"(dst_u32), "l"(src_ptr) : "memory")
#define CP_COMMIT()  asm volatile("cp.async.commit_group;" ::: "memory")
#define CP_WAIT(N)   asm volatile("cp.async.wait_group %0;" :: "n"(N) : "memory")

#define LDSM_X4(r, addr) \
    asm volatile("ldmatrix.sync.aligned.m8n8.x4.shared.b16 {%0,%1,%2,%3}, [%4];" \
                 : "=r"((r)[0]), "=r"((r)[1]), "=r"((r)[2]), "=r"((r)[3]) \
                 : "r"(addr))
#define LDSM_X2(r, addr) \
    asm volatile("ldmatrix.sync.aligned.m8n8.x2.shared.b16 {%0,%1}, [%2];" \
                 : "=r"((r)[0]), "=r"((r)[1]) : "r"(addr))

// D(16x8,f32) += A(16x16,bf16,row) * B(16x8,bf16,col)
#define MMA_BF16(d, a, b) \
    asm volatile("mma.sync.aligned.m16n8k16.row.col.f32.bf16.bf16.f32 " \
                 "{%0,%1,%2,%3}, {%4,%5,%6,%7}, {%8,%9}, {%0,%1,%2,%3};" \
                 : "+f"((d)[0]), "+f"((d)[1]), "+f"((d)[2]), "+f"((d)[3]) \
                 : "r"((a)[0]), "r"((a)[1]), "r"((a)[2]), "r"((a)[3]), \
                   "r"((b)[0]), "r"((b)[1]))

// ---------------------------------------------------------------------------
// Split kernels: fp32 -> 2 bf16 components (x ~= b0 + b1, residual ~2^-18 rel)
// GEMM uses 3 cross products (00,01,10); dropped a1*b1 ~ 2^-18 per term.
// Resulting |h_noisy - h_exact| ~ 4e-6 << DELTA/2; decisions fixed by band.
// ---------------------------------------------------------------------------
__global__ void split_x_kernel(const float* __restrict__ src) {
    int i = blockIdx.x * blockDim.x + threadIdx.x;
    if (i >= BATCH * IN_DIM) return;
    float v = src[i];
    __nv_bfloat16 b0 = __float2bfloat16(v);
    __nv_bfloat16 b1 = __float2bfloat16(v - __bfloat162float(b0));
    g_xs[0][i] = b0; g_xs[1][i] = b1;
}

__global__ void split_w_kernel(const float* __restrict__ src) {
    int i = blockIdx.x * blockDim.x + threadIdx.x;
    if (i >= HID_DIM * IN_DIM) return;
    float v = src[i];
    __nv_bfloat16 b0 = __float2bfloat16(v);
    __nv_bfloat16 b1 = __float2bfloat16(v - __bfloat162float(b0));
    g_ws[0][i] = b0; g_ws[1][i] = b1;
}

// ---------------------------------------------------------------------------
// Kernel 0: transpose dec_w (OUT x HID) -> g_dwt (HID x OUT)
// ---------------------------------------------------------------------------
__global__ void transpose_kernel(const float* __restrict__ dw) {
    __shared__ float tile[32][33];
    const int n0 = blockIdx.x * 32;
    const int o0 = blockIdx.y * 32;
    const int tx = threadIdx.x;
    const int ty = threadIdx.y;
#pragma unroll
    for (int j = 0; j < 4; j++) {
        tile[ty + j * 8][tx] =
            dw[(size_t)(o0 + ty + j * 8) * HID_DIM + n0 + tx];
    }
    __syncthreads();
#pragma unroll
    for (int j = 0; j < 4; j++) {
        g_dwt[(size_t)(n0 + ty + j * 8) * OUT_DIM + o0 + tx] =
            tile[tx][ty + j * 8];
    }
}

// ---------------------------------------------------------------------------
// Kernel 1: HMMA bf16 2-split / 3-product GEMM (abs err ~4e-6)
//   h[m][n] = relu( sum_k x[m][k]*enc_w[n][k] + enc_b[n] )
// 128x128 CTA, 8 warps (32x64 each), K in 4 chunks of 64, cp.async double
// buffer of 4 bf16 planes (a0,a1,b0,b1), products (a0b0)(a0b1)(a1b0).
// ---------------------------------------------------------------------------
#define STRIDE_B     144                        // 64 bf16 = 128B + 16B pad
#define PLANE_BYTES  (128 * STRIDE_B)           // 18432
#define BUF_BYTES    (4 * PLANE_BYTES)          // 73728
#define GEMM_SMEM    (2 * BUF_BYTES)            // 147456

__global__ __launch_bounds__(256, 1)
void gemm_mma_kernel(const float* __restrict__ bias, float* __restrict__ C) {
    extern __shared__ unsigned char smem[];
    const uint32_t sb = smem_to_u32(smem);
    const int t = threadIdx.x;
    const int wid = t >> 5;
    const int lane = t & 31;
    const int bm = blockIdx.y * 128;
    const int bn = blockIdx.x * 128;
    const int m0 = (wid & 3) * 32;              // warp row base within tile
    const int n0 = (wid >> 2) * 64;             // warp col base within tile

    const __nv_bfloat16* planes[4] = {
        g_xs[0] + (size_t)bm * IN_DIM, g_xs[1] + (size_t)bm * IN_DIM,
        g_ws[0] + (size_t)bn * IN_DIM, g_ws[1] + (size_t)bn * IN_DIM };

    float acc[2][8][4];
#pragma unroll
    for (int mt = 0; mt < 2; mt++)
#pragma unroll
        for (int nt = 0; nt < 8; nt++)
#pragma unroll
            for (int i = 0; i < 4; i++) acc[mt][nt][i] = 0.0f;

    auto load_chunk = [&](int buf, int c) {
#pragma unroll
        for (int p = 0; p < 4; p++) {
            const unsigned char* srcp = (const unsigned char*)planes[p];
#pragma unroll
            for (int i = 0; i < 4; i++) {
                int g = i * 256 + t;            // 0..1023 16B units
                int row = g >> 3;
                int seg = g & 7;
                const unsigned char* src =
                    srcp + ((size_t)row * IN_DIM + c * 64 + seg * 8) * 2;
                uint32_t dst = sb + buf * BUF_BYTES + p * PLANE_BYTES +
                               row * STRIDE_B + seg * 16;
                CP_ASYNC16(dst, src);
            }
        }
        CP_COMMIT();
    };

    auto compute_chunk = [&](int buf) {
        const uint32_t ab = sb + buf * BUF_BYTES;
#pragma unroll
        for (int j = 0; j < 4; j++) {           // k-steps of 16
            uint32_t af[2][2][4];
#pragma unroll
            for (int ap = 0; ap < 2; ap++)
#pragma unroll
                for (int mt = 0; mt < 2; mt++) {
                    uint32_t addr = ab + ap * PLANE_BYTES +
                        (uint32_t)(m0 + 16 * mt + (lane & 15)) * STRIDE_B +
                        j * 32 + (lane >> 4) * 16;
                    LDSM_X4(af[ap][mt], addr);
                }
#pragma unroll
            for (int bp = 0; bp < 2; bp++) {
                uint32_t bf[8][2];
                const int l = lane & 15;
#pragma unroll
                for (int nt = 0; nt < 8; nt++) {
                    uint32_t addr = ab + (2 + bp) * PLANE_BYTES +
                        (uint32_t)(n0 + 8 * nt + (l & 7)) * STRIDE_B +
                        j * 32 + (l >> 3) * 16;
                    LDSM_X2(bf[nt], addr);
                }
                const int na = (bp == 0) ? 2 : 1;   // (a0,b0)(a1,b0);(a0,b1)
#pragma unroll
                for (int ap = 0; ap < 2; ap++) {
                    if (ap >= na) break;
#pragma unroll
                    for (int mt = 0; mt < 2; mt++)
#pragma unroll
                        for (int nt = 0; nt < 8; nt++)
                            MMA_BF16(acc[mt][nt], af[ap][mt], bf[nt]);
                }
            }
        }
    };

    load_chunk(0, 0);
    load_chunk(1, 1);

    CP_WAIT(1); __syncthreads();
    compute_chunk(0);
    __syncthreads();
    load_chunk(0, 2);

    CP_WAIT(1); __syncthreads();
    compute_chunk(1);
    __syncthreads();
    load_chunk(1, 3);

    CP_WAIT(1); __syncthreads();
    compute_chunk(0);

    CP_WAIT(0); __syncthreads();
    compute_chunk(1);

    // ---- epilogue: + bias, relu, store
#pragma unroll
    for (int mt = 0; mt < 2; mt++) {
        const int r0 = bm + m0 + 16 * mt + (lane >> 2);
#pragma unroll
        for (int nt = 0; nt < 8; nt++) {
            const int col = bn + n0 + 8 * nt + 2 * (lane & 3);
            const float bv0 = __ldg(bias + col);
            const float bv1 = __ldg(bias + col + 1);
            float2 v0, v1;
            v0.x = fmaxf(acc[mt][nt][0] + bv0, 0.0f);
            v0.y = fmaxf(acc[mt][nt][1] + bv1, 0.0f);
            v1.x = fmaxf(acc[mt][nt][2] + bv0, 0.0f);
            v1.y = fmaxf(acc[mt][nt][3] + bv1, 0.0f);
            *(float2*)&C[(size_t)r0 * HID_DIM + col] = v0;
            *(float2*)&C[(size_t)(r0 + 8) * HID_DIM + col] = v1;
        }
    }
}

// ---------------------------------------------------------------------------
// Kernel 2 (fused): radix top-k on noisy h + exact boundary-band recheck +
// masked writeback + sparse decoder GEMM.  One CTA (256 threads) per row.
//
// Restructured vs R9: no 64KB keys[] (row re-read from L2 each phase);
// round-1 exponent-byte histogram uses warp-aggregated (__match_any_sync)
// atomics with the relu-zero bin skipped; rounds 2-4 run on a compacted
// candidate list (threshold-byte bin, ~370 values) in smem.  Threshold is
// bit-identical to the old 4-round radix.  ~26KB smem -> 8 CTAs/SM.
// ---------------------------------------------------------------------------
#define DELTA     1e-2f
#define BAND_CAP  256
#define CAND_CAP  4096
#define KEEP_CAP  512

struct FusedSmem {
    float        x_row[IN_DIM];        //  1KB
    unsigned int hist[256];            //  1KB
    unsigned int cand[CAND_CAP];       // 16KB
    float        band_exact[BAND_CAP]; //  1KB
    int          band_idx[BAND_CAP];   //  1KB
    int          band_keep[BAND_CAP];  //  1KB
    float        vals[KEEP_CAP];       //  2KB
    int          idxs[KEEP_CAP];       //  2KB
    int          cnt;
    unsigned int sh_prefix;
    int          sh_krem;
    int          n_hi;
    int          band_cnt;
    int          ccnt;
};

__global__ __launch_bounds__(256)
void fused_topk_decode_kernel(float* __restrict__ hid,
                              const float* __restrict__ x,
                              const float* __restrict__ enc_w,
                              const float* __restrict__ enc_b,
                              const float* __restrict__ dec_b,
                              float* __restrict__ out) {
    extern __shared__ unsigned char smem_raw[];
    FusedSmem& s = *reinterpret_cast<FusedSmem*>(smem_raw);

    const int t = threadIdx.x;            // 0..255
    const int wid = t >> 5;
    const int lane = t & 31;
    const int row = blockIdx.x;
    float* hrow = hid + (size_t)row * HID_DIM;
    const float4* hrow4 = (const float4*)hrow;

    s.x_row[t] = x[(size_t)row * IN_DIM + t];
    s.hist[t] = 0;
    if (t == 0) { s.ccnt = 0; s.n_hi = 0; s.band_cnt = 0; s.cnt = 0; }
    __syncthreads();

    // ---- Phase A: exponent-byte histogram, warp-aggregated, zeros skipped
#pragma unroll 4
    for (int i = 0; i < 16; i++) {
        float4 v = hrow4[i * 256 + t];
        unsigned int k4[4] = { __float_as_uint(v.x), __float_as_uint(v.y),
                               __float_as_uint(v.z), __float_as_uint(v.w) };
#pragma unroll
        for (int c = 0; c < 4; c++) {
            unsigned int bin = k4[c] >> 24;            // sign=0 for relu'd h
            unsigned int grp = __match_any_sync(0xFFFFFFFFu, bin);
            int leader = __ffs(grp) - 1;
            if (lane == leader && bin)
                atomicAdd(&s.hist[bin], (unsigned int)__popc(grp));
        }
    }
    __syncthreads();

    // ---- Phase B: walk byte-1 histogram from the top
    if (t == 0) {
        unsigned int cum = 0;
        int d = 255;
        for (; d > 0; d--) {
            unsigned int c = s.hist[d];
            if (cum + c >= (unsigned int)TOPK) break;
            cum += c;
        }
        s.sh_prefix = (unsigned int)d << 24;
        s.sh_krem = TOPK - (int)cum;
    }
    __syncthreads();
    unsigned int prefix = s.sh_prefix;
    int krem = s.sh_krem;
    unsigned int maskhi = 0xFF000000u;

    if (prefix == 0u) {
        // Degenerate (fewer than k positive values): thr = 0, keep-all.
        // hidden_post == h (already in hrow).  Dense decode.
        float acc = 0.0f;
        for (int j = 0; j < HID_DIM; j++) {
            float v = __ldg(hrow + j);
            if (v != 0.0f)
                acc = fmaf(v, g_dwt[(size_t)j * OUT_DIM + t], acc);
        }
        out[(size_t)row * OUT_DIM + t] = acc + dec_b[t];
        return;
    }

    // ---- Phase C: compact candidates of the threshold byte-bin
    const unsigned int dbyte = prefix >> 24;
#pragma unroll 4
    for (int i = 0; i < 16; i++) {
        float4 v = hrow4[i * 256 + t];
        unsigned int k4[4] = { __float_as_uint(v.x), __float_as_uint(v.y),
                               __float_as_uint(v.z), __float_as_uint(v.w) };
#pragma unroll
        for (int c = 0; c < 4; c++) {
            if ((k4[c] >> 24) == dbyte && k4[c]) {
                int p = atomicAdd(&s.ccnt, 1);
                if (p < CAND_CAP) s.cand[p] = k4[c];
            }
        }
    }
    __syncthreads();
    const int nc = min(s.ccnt, CAND_CAP);
    const bool overflow = (s.ccnt > CAND_CAP);

    // ---- rounds 2..4 of the radix select
#pragma unroll 1
    for (int r = 1; r < 4; r++) {
        const int shift = 24 - r * 8;
        s.hist[t] = 0;
        __syncthreads();
        if (!overflow) {
            for (int i = t; i < nc; i += 256) {
                unsigned int key = s.cand[i];
                if ((key & maskhi) == prefix)
                    atomicAdd(&s.hist[(key >> shift) & 255u], 1u);
            }
        } else {
            // rare fallback: stream from gmem with aggregated atomics
#pragma unroll 4
            for (int i = 0; i < 16; i++) {
                float4 v = hrow4[i * 256 + t];
                unsigned int k4[4] = { __float_as_uint(v.x), __float_as_uint(v.y),
                                       __float_as_uint(v.z), __float_as_uint(v.w) };
#pragma unroll
                for (int c = 0; c < 4; c++) {
                    bool ok = ((k4[c] & maskhi) == prefix);
                    unsigned int bin = ok ? ((k4[c] >> shift) & 255u) : 0xFFFFu;
                    unsigned int grp = __match_any_sync(0xFFFFFFFFu, bin);
                    int leader = __ffs(grp) - 1;
                    if (lane == leader && ok)
                        atomicAdd(&s.hist[bin], (unsigned int)__popc(grp));
                }
            }
        }
        __syncthreads();
        if (t == 0) {
            unsigned int cum = 0;
            int d = 255;
            for (; d > 0; d--) {
                unsigned int c = s.hist[d];
                if (cum + c >= (unsigned int)krem) break;
                cum += c;
            }
            s.sh_prefix = prefix | ((unsigned int)d << shift);
            s.sh_krem = krem - (int)cum;
        }
        __syncthreads();
        prefix = s.sh_prefix;
        krem = s.sh_krem;
        maskhi |= (0xFFu << shift);
    }
    const float thr = __uint_as_float(prefix);
    const float thr_hi = thr + DELTA;
    const float thr_lo = thr - DELTA;

    // ---- Phase D: count sure-keeps, collect boundary-band candidates
    {
        int my_hi = 0;
#pragma unroll 4
        for (int i = 0; i < 16; i++) {
            float4 v4 = hrow4[i * 256 + t];
            float vv[4] = { v4.x, v4.y, v4.z, v4.w };
#pragma unroll
            for (int c = 0; c < 4; c++) {
                float v = vv[c];
                if (v > thr_hi) {
                    my_hi++;
                } else if (v >= thr_lo) {
                    int p = atomicAdd(&s.band_cnt, 1);
                    if (p < BAND_CAP) s.band_idx[p] = (i * 256 + t) * 4 + c;
                }
            }
        }
#pragma unroll
        for (int off = 16; off; off >>= 1)
            my_hi += __shfl_xor_sync(0xFFFFFFFFu, my_hi, off);
        if (lane == 0 && my_hi) atomicAdd(&s.n_hi, my_hi);
    }
    __syncthreads();
    const int bc = min(s.band_cnt, BAND_CAP);
    const int n_hi = s.n_hi;

    // ---- Phase E: exact fp32 recompute of band candidates (warp per cand)
    for (int b = wid; b < bc; b += 8) {
        const int n = s.band_idx[b];
        const float* wrow = enc_w + (size_t)n * IN_DIM;
        float4 xa = *(const float4*)&s.x_row[lane * 8];
        float4 xb = *(const float4*)&s.x_row[lane * 8 + 4];
        float4 wa = *(const float4*)&wrow[lane * 8];
        float4 wb = *(const float4*)&wrow[lane * 8 + 4];
        float p = xa.x * wa.x;
        p = fmaf(xa.y, wa.y, p);
        p = fmaf(xa.z, wa.z, p);
        p = fmaf(xa.w, wa.w, p);
        p = fmaf(xb.x, wb.x, p);
        p = fmaf(xb.y, wb.y, p);
        p = fmaf(xb.z, wb.z, p);
        p = fmaf(xb.w, wb.w, p);
#pragma unroll
        for (int off = 16; off; off >>= 1)
            p += __shfl_xor_sync(0xFFFFFFFFu, p, off);
        if (lane == 0)
            s.band_exact[b] = fmaxf(p + __ldg(enc_b + n), 0.0f);
    }
    __syncthreads();

    // ---- Phase F: keep top (TOPK - n_hi) band values, >= ties kept
    if (wid == 0) {
        const int kr = TOPK - n_hi;   // >= 1 by construction
        for (int i = lane; i < bc; i += 32) {
            float ei = s.band_exact[i];
            int cnt = 0;
            for (int j = 0; j < bc; j++)
                cnt += (s.band_exact[j] > ei) ? 1 : 0;
            s.band_keep[i] = (cnt < kr) ? 1 : 0;
        }
    }
    __syncthreads();

    // ---- Phase G: masked writeback + keep compaction
#pragma unroll 2
    for (int i = 0; i < 16; i++) {
        float4 v4 = hrow4[i * 256 + t];
        float vv[4] = { v4.x, v4.y, v4.z, v4.w };
        float ov[4];
#pragma unroll
        for (int c = 0; c < 4; c++) {
            float v = vv[c];
            int n = (i * 256 + t) * 4 + c;
            bool keep;
            float outv;
            if (v > thr_hi) {
                keep = true; outv = v;
            } else if (v >= thr_lo) {
                keep = false; outv = 0.0f;
                for (int b = 0; b < bc; b++) {
                    if (s.band_idx[b] == n) {
                        keep = (s.band_keep[b] != 0);
                        outv = s.band_exact[b];
                        break;
                    }
                }
                if (!keep) outv = 0.0f;
            } else {
                keep = false; outv = 0.0f;
            }
            ov[c] = keep ? outv : 0.0f;
            if (keep) {
                int p = atomicAdd(&s.cnt, 1);
                if (p < KEEP_CAP) { s.vals[p] = outv; s.idxs[p] = n; }
            }
        }
        ((float4*)hrow)[i * 256 + t] = make_float4(ov[0], ov[1], ov[2], ov[3]);
    }
    __syncthreads();

    // ---- sparse decode over compacted keeps
    const int m = min(s.cnt, KEEP_CAP);
    float acc = 0.0f;
#pragma unroll 8
    for (int j = 0; j < m; j++) {
        acc = fmaf(s.vals[j], g_dwt[(size_t)s.idxs[j] * OUT_DIM + t], acc);
    }
    out[(size_t)row * OUT_DIM + t] = acc + dec_b[t];
}

// ---------------------------------------------------------------------------
// kernel_launch
//   inputs: 0=x, 1=enc_w, 2=enc_b, 3=dec_w, 4=dec_b, 5=k (fixed 256)
//   output: [output (8192*256) | hidden_post (8192*16384)] fp32
// ---------------------------------------------------------------------------
extern "C" void kernel_launch(void* const* d_in, const int* in_sizes, int n_in,
                              void* d_out, int out_size) {
    const float* x     = (const float*)d_in[0];
    const float* enc_w = (const float*)d_in[1];
    const float* enc_b = (const float*)d_in[2];
    const float* dec_w = (const float*)d_in[3];
    const float* dec_b = (const float*)d_in[4];

    float* out = (float*)d_out;
    float* hid = out + (size_t)BATCH * OUT_DIM;

    // idempotent attribute setup (host-side, not captured)
    cudaFuncSetAttribute(fused_topk_decode_kernel,
                         cudaFuncAttributeMaxDynamicSharedMemorySize,
                         (int)sizeof(FusedSmem));
    cudaFuncSetAttribute(gemm_mma_kernel,
                         cudaFuncAttributeMaxDynamicSharedMemorySize,
                         GEMM_SMEM);

    // prep: 2-way bf16 splits of x and enc_w; dec_w transpose
    split_x_kernel<<<(BATCH * IN_DIM + 255) / 256, 256>>>(x);
    split_w_kernel<<<(HID_DIM * IN_DIM + 255) / 256, 256>>>(enc_w);
    transpose_kernel<<<dim3(HID_DIM / 32, OUT_DIM / 32), dim3(32, 8)>>>(dec_w);

    // k1: HMMA bf16 2-split / 3-product encoder GEMM + bias + relu
    gemm_mma_kernel<<<dim3(HID_DIM / 128, BATCH / 128), 256, GEMM_SMEM>>>(enc_b, hid);

    // k2: fused top-k with exact boundary-band recheck + sparse decoder GEMM
    fused_topk_decode_kernel<<<BATCH, 256, sizeof(FusedSmem)>>>(
        hid, x, enc_w, enc_b, dec_b, out);
}